// round 6
// baseline (speedup 1.0000x reference)
#include <cuda_runtime.h>
#include <cuda_bf16.h>
#include <cstdint>

#define G_NUM 128
#define C_NUM 256
#define D_NUM 128
#define N_NODES_C 262144

// Scratch (device globals — no allocation allowed)
__device__ uint32_t g_cent[C_NUM * (D_NUM / 2)];   // centroids as packed bf16 pairs
__device__ float    g_c_sq[C_NUM];
__device__ float    g_sums[G_NUM * C_NUM];
__device__ int      g_counts[G_NUM];

// ---------------------------------------------------------------------------
__global__ void zero_sums_kernel() {
    int i = blockIdx.x * blockDim.x + threadIdx.x;
    if (i < G_NUM * C_NUM) g_sums[i] = 0.f;
}

// one block (32 threads) per centroid: convert to bf16, compute c_sq from bf16
__global__ void prep_cent_kernel(const float* __restrict__ cent) {
    int c = blockIdx.x;
    int t = threadIdx.x;  // 0..31
    float4 v = ((const float4*)cent)[c * 32 + t];
    __nv_bfloat162 p0 = __floats2bfloat162_rn(v.x, v.y);
    __nv_bfloat162 p1 = __floats2bfloat162_rn(v.z, v.w);
    g_cent[c * 64 + t * 2]     = *(uint32_t*)&p0;
    g_cent[c * 64 + t * 2 + 1] = *(uint32_t*)&p1;
    float a = __bfloat162float(p0.x), b = __bfloat162float(p0.y);
    float e = __bfloat162float(p1.x), f = __bfloat162float(p1.y);
    float s = a * a + b * b + e * e + f * f;
    #pragma unroll
    for (int off = 16; off; off >>= 1) s += __shfl_down_sync(0xffffffffu, s, off);
    if (t == 0) g_c_sq[c] = s;
}

// batch is sorted: per-graph counts via binary search (no atomics)
__global__ void counts_kernel(const int* __restrict__ batch) {
    int g = threadIdx.x;  // 0..127
    if (g >= G_NUM) return;
    int lo = 0, hi = N_NODES_C;
    while (lo < hi) { int m = (lo + hi) >> 1; if (batch[m] < g) lo = m + 1; else hi = m; }
    int a = lo, b = N_NODES_C;
    while (a < b) { int m = (a + b) >> 1; if (batch[m] < g + 1) a = m + 1; else b = m; }
    g_counts[g] = a - lo;
}

// ---------------------------------------------------------------------------
// Main: 128 (nodes) x 128 (centroids) tile per block; K=128 fully staged.
// 8 warps in 4(M) x 2(N); each warp: 32x64 via mma.m16n8k16 bf16.
// Fragments loaded with ldmatrix.m8n8.x4 (identical layout to scalar version).
#define SA_STRIDE 68    // u32 per row (= 272 B; padding kills bank conflicts)
#define SA_BYTES  (SA_STRIDE * 4)
#define SD_STRIDE 132   // floats per row for dist tile
#define SMEM_BYTES 71168

__global__ void __launch_bounds__(256, 2)
centroid_main_kernel(const float* __restrict__ x, const int* __restrict__ batch) {
    extern __shared__ char smem[];
    uint32_t* sA = (uint32_t*)smem;          // 128*68 u32 = 34816 B (bf16 x tile)
    uint32_t* sB = sA + 128 * SA_STRIDE;     // 34816 B (bf16 centroid tile)
    float*    sD = (float*)smem;             // aliases sA/sB after sync (67584 B)
    float* sXsq   = (float*)(smem + 69632);  // 128 f32
    float* sCsq   = (float*)(smem + 70144);  // 128 f32
    int*   sBatch = (int*)  (smem + 70656);  // 128 i32

    const int tid  = threadIdx.x;
    const int lane = tid & 31;
    const int warp = tid >> 5;
    const int by = blockIdx.x;     // centroid half (0/1)  [fast dim -> pair co-scheduled]
    const int bm = blockIdx.y;     // node tile (2048)
    const int wm = (warp >> 1) * 32;
    const int wn = (warp & 1) * 64;
    const int gid = lane >> 2;     // 0..7
    const int kq  = lane & 3;      // 0..3

    // Load centroid tile (already bf16-packed): 8192 u32, coalesced
    {
        const uint32_t* src = g_cent + (size_t)by * 128 * 64;
        #pragma unroll
        for (int i = 0; i < 32; i++) {
            int idx = tid + i * 256;            // 0..8191
            int row = idx >> 6, cp = idx & 63;
            sB[row * SA_STRIDE + cp] = src[idx];
        }
    }
    // Load x tile (fp32 -> bf16), coalesced float4
    {
        const float4* src = (const float4*)(x + (size_t)bm * 128 * 128);
        #pragma unroll
        for (int i = 0; i < 16; i++) {
            int fidx = i * 1024 + tid * 4;
            float4 v = src[fidx >> 2];
            int row = fidx >> 7, col = fidx & 127;
            __nv_bfloat162 p0 = __floats2bfloat162_rn(v.x, v.y);
            __nv_bfloat162 p1 = __floats2bfloat162_rn(v.z, v.w);
            uint2 pk = make_uint2(*(uint32_t*)&p0, *(uint32_t*)&p1);
            *(uint2*)&sA[row * SA_STRIDE + (col >> 1)] = pk;
        }
    }
    if (tid < 128) {
        sBatch[tid] = batch[bm * 128 + tid];
        sCsq[tid]   = g_c_sq[by * 128 + tid];
    }
    __syncthreads();

    // x_sq from the bf16-quantized data (exact Gram identity), vectorized
    if (tid < 128) {
        float s = 0.f;
        const uint4* rp = (const uint4*)(sA + tid * SA_STRIDE);
        #pragma unroll
        for (int j = 0; j < 16; j++) {
            uint4 v = rp[j];
            uint32_t w[4] = {v.x, v.y, v.z, v.w};
            #pragma unroll
            for (int q = 0; q < 4; q++) {
                __nv_bfloat162 h = *(__nv_bfloat162*)&w[q];
                float a = __bfloat162float(h.x), b = __bfloat162float(h.y);
                s = fmaf(a, a, s); s = fmaf(b, b, s);
            }
        }
        sXsq[tid] = s;
    }

    // ldmatrix per-lane base addresses (shared-space u32)
    const uint32_t smem_u32 = (uint32_t)__cvta_generic_to_shared(smem);
    const uint32_t sA_b = smem_u32;
    const uint32_t sB_b = smem_u32 + 128 * SA_BYTES;
    const int i8 = lane >> 3, j8 = lane & 7;
    uint32_t aAddr[2], bAddr[4];
    #pragma unroll
    for (int mt = 0; mt < 2; mt++) {
        int row = wm + mt * 16 + j8 + (i8 & 1) * 8;
        aAddr[mt] = sA_b + row * SA_BYTES + (i8 >> 1) * 16;
    }
    #pragma unroll
    for (int p = 0; p < 4; p++) {
        int row = wn + p * 16 + j8 + (i8 >> 1) * 8;
        bAddr[p] = sB_b + row * SA_BYTES + (i8 & 1) * 16;
    }

    float acc[2][8][4];
    #pragma unroll
    for (int mt = 0; mt < 2; mt++)
        #pragma unroll
        for (int nt = 0; nt < 8; nt++)
            #pragma unroll
            for (int q = 0; q < 4; q++) acc[mt][nt][q] = 0.f;

    #pragma unroll
    for (int ks = 0; ks < 8; ks++) {
        const uint32_t koff = ks * 32;   // 16 bf16 = 32 B per k-step
        uint32_t afr[2][4], bfr[4][4];
        #pragma unroll
        for (int mt = 0; mt < 2; mt++) {
            asm volatile(
                "ldmatrix.sync.aligned.m8n8.x4.shared.b16 {%0,%1,%2,%3}, [%4];\n"
                : "=r"(afr[mt][0]), "=r"(afr[mt][1]), "=r"(afr[mt][2]), "=r"(afr[mt][3])
                : "r"(aAddr[mt] + koff));
        }
        #pragma unroll
        for (int p = 0; p < 4; p++) {
            asm volatile(
                "ldmatrix.sync.aligned.m8n8.x4.shared.b16 {%0,%1,%2,%3}, [%4];\n"
                : "=r"(bfr[p][0]), "=r"(bfr[p][1]), "=r"(bfr[p][2]), "=r"(bfr[p][3])
                : "r"(bAddr[p] + koff));
        }
        #pragma unroll
        for (int p = 0; p < 4; p++) {
            #pragma unroll
            for (int half = 0; half < 2; half++) {
                const int nt = p * 2 + half;
                const uint32_t b0 = bfr[p][half * 2];
                const uint32_t b1 = bfr[p][half * 2 + 1];
                #pragma unroll
                for (int mt = 0; mt < 2; mt++) {
                    asm volatile(
                        "mma.sync.aligned.m16n8k16.row.col.f32.bf16.bf16.f32 "
                        "{%0,%1,%2,%3}, {%4,%5,%6,%7}, {%8,%9}, {%0,%1,%2,%3};\n"
                        : "+f"(acc[mt][nt][0]), "+f"(acc[mt][nt][1]),
                          "+f"(acc[mt][nt][2]), "+f"(acc[mt][nt][3])
                        : "r"(afr[mt][0]), "r"(afr[mt][1]), "r"(afr[mt][2]), "r"(afr[mt][3]),
                          "r"(b0), "r"(b1));
                }
            }
        }
    }
    __syncthreads();   // sA/sB reads done; sXsq visible to all

    // Epilogue: distance -> sD (aliases sA/sB)
    #pragma unroll
    for (int mt = 0; mt < 2; mt++) {
        int r = wm + mt * 16 + gid;
        float xs0 = sXsq[r], xs1 = sXsq[r + 8];
        #pragma unroll
        for (int nt = 0; nt < 8; nt++) {
            int c = wn + nt * 8 + kq * 2;
            float cs0 = sCsq[c], cs1 = sCsq[c + 1];
            float d00 = fmaxf(xs0 + cs0 - 2.f * acc[mt][nt][0], 0.f);
            float d01 = fmaxf(xs0 + cs1 - 2.f * acc[mt][nt][1], 0.f);
            float d10 = fmaxf(xs1 + cs0 - 2.f * acc[mt][nt][2], 0.f);
            float d11 = fmaxf(xs1 + cs1 - 2.f * acc[mt][nt][3], 0.f);
            *(float2*)&sD[r * SD_STRIDE + c]       = make_float2(sqrtf(d00), sqrtf(d01));
            *(float2*)&sD[(r + 8) * SD_STRIDE + c] = make_float2(sqrtf(d10), sqrtf(d11));
        }
    }
    __syncthreads();

    // Segmented per-column reduction (batch sorted -> few atomics per column)
    {
        int col = tid & 127;
        int rh  = tid >> 7;            // uniform per warp
        int rbase = rh * 64;
        float accum = 0.f;
        int curg = sBatch[rbase];
        #pragma unroll 4
        for (int r = rbase; r < rbase + 64; r++) {
            int gg = sBatch[r];
            if (gg != curg) {
                atomicAdd(&g_sums[curg * C_NUM + by * 128 + col], accum);
                accum = 0.f; curg = gg;
            }
            accum += sD[r * SD_STRIDE + col];
        }
        atomicAdd(&g_sums[curg * C_NUM + by * 128 + col], accum);
    }
}

// ---------------------------------------------------------------------------
__global__ void finalize_kernel(float* __restrict__ out) {
    int g = blockIdx.x, c = threadIdx.x;
    float cnt = (float)(g_counts[g] > 1 ? g_counts[g] : 1);
    out[g * C_NUM + c] = g_sums[g * C_NUM + c] / cnt;
}

// ---------------------------------------------------------------------------
extern "C" void kernel_launch(void* const* d_in, const int* in_sizes, int n_in,
                              void* d_out, int out_size) {
    const float* x     = (const float*)d_in[0];
    const int*   batch = (const int*)d_in[1];
    const float* cent  = (const float*)d_in[2];
    float* out = (float*)d_out;

    cudaFuncSetAttribute(centroid_main_kernel,
                         cudaFuncAttributeMaxDynamicSharedMemorySize, SMEM_BYTES);

    zero_sums_kernel<<<128, 256>>>();
    prep_cent_kernel<<<C_NUM, 32>>>(cent);
    counts_kernel<<<1, 128>>>(batch);
    // grid.x = centroid half (fast dim) so the (by=0, by=1) pair sharing an
    // x-tile is adjacent in launch order -> second read hits L2.
    dim3 grid(2, N_NODES_C / 128);
    centroid_main_kernel<<<grid, 256, SMEM_BYTES>>>(x, batch);
    finalize_kernel<<<G_NUM, 256>>>(out);
}

// round 8
// speedup vs baseline: 1.0715x; 1.0715x over previous
#include <cuda_runtime.h>
#include <cuda_bf16.h>
#include <cstdint>

#define G_NUM 128
#define C_NUM 256
#define N_NODES_C 262144
#define N_TILES 2048
#define GRID_MAIN 148
#define THREADS 512

// Scratch (device globals — no allocation allowed)
__device__ uint32_t g_cent[C_NUM * 64];   // centroids as packed bf16 pairs
__device__ float    g_c_sq[C_NUM];
__device__ float    g_sums[G_NUM * C_NUM];
__device__ int      g_counts[G_NUM];

// ---------------------------------------------------------------------------
// smem layout (bytes)
#define OFF_SA    0         // 128 rows x 272B (bf16 x-tile, padded for ldmatrix)
#define OFF_SB    34816     // 256 rows x 272B (bf16 centroids, padded)
#define OFF_STAGE 104448    // 128 rows x 512B (raw f32 tile, cp.async target)
#define OFF_DIST  169984    // 128 rows x 256B (bf16 dist chunk, XOR-swizzled)
#define OFF_XSQ   202752    // 128 f32
#define OFF_CSQ   203264    // 256 f32
#define OFF_BAT   204288    // 128 i32
#define SMEM_TOTAL 204800
#define SA_STRIDE_B 272

#define CP_COMMIT() asm volatile("cp.async.commit_group;" ::: "memory")
#define CP_WAIT0()  asm volatile("cp.async.wait_group 0;" ::: "memory")

__device__ __forceinline__ float fsqrt_approx(float v) {
    float r; asm("sqrt.approx.f32 %0, %1;" : "=f"(r) : "f"(v)); return r;
}

// ---------------------------------------------------------------------------
// Prep: zero sums, convert centroids to bf16 (+c_sq), counts via binary search
// grid 256 x 256 threads
__global__ void prep_kernel(const float* __restrict__ cent, const int* __restrict__ batch) {
    int b = blockIdx.x, t = threadIdx.x;
    if (t < 128) g_sums[b * 128 + t] = 0.f;
    if (t < 32) {
        float4 v = ((const float4*)cent)[b * 32 + t];
        __nv_bfloat162 p0 = __floats2bfloat162_rn(v.x, v.y);
        __nv_bfloat162 p1 = __floats2bfloat162_rn(v.z, v.w);
        g_cent[b * 64 + t * 2]     = *(uint32_t*)&p0;
        g_cent[b * 64 + t * 2 + 1] = *(uint32_t*)&p1;
        float a = __bfloat162float(p0.x), c = __bfloat162float(p0.y);
        float e = __bfloat162float(p1.x), f = __bfloat162float(p1.y);
        float s = a * a + c * c + e * e + f * f;
        #pragma unroll
        for (int off = 16; off; off >>= 1) s += __shfl_down_sync(0xffffffffu, s, off);
        if (t == 0) g_c_sq[b] = s;
    }
    if (b == 0 && t >= 128 && t < 256) {
        int g = t - 128;
        int lo = 0, hi = N_NODES_C;
        while (lo < hi) { int m = (lo + hi) >> 1; if (batch[m] < g) lo = m + 1; else hi = m; }
        int a2 = lo, b2 = N_NODES_C;
        while (a2 < b2) { int m = (a2 + b2) >> 1; if (batch[m] < g + 1) a2 = m + 1; else b2 = m; }
        g_counts[g] = a2 - lo;
    }
}

// ---------------------------------------------------------------------------
// Main: persistent 1 CTA/SM, 512 threads (16 warps, 4M x 4N layout).
// Per tile: 128 nodes x 256 centroids, K=128, mma.sync m16n8k16 bf16.
// ---------------------------------------------------------------------------
__global__ void __launch_bounds__(THREADS, 1)
centroid_main_kernel(const float* __restrict__ x, const int* __restrict__ batch) {
    extern __shared__ char smem[];
    const uint32_t sbase = (uint32_t)__cvta_generic_to_shared(smem);
    float* sXsq = (float*)(smem + OFF_XSQ);
    float* sCsq = (float*)(smem + OFF_CSQ);
    int*   sBat = (int*)  (smem + OFF_BAT);
    uint32_t* sDistW = (uint32_t*)(smem + OFF_DIST);

    const int tid  = threadIdx.x;
    const int lane = tid & 31;
    const int warp = tid >> 5;
    const int wm = (warp & 3) * 32;     // M band (warp&3 = SMSP)
    const int wn = (warp >> 2) * 64;    // N band
    const int gid = lane >> 2;          // 0..7
    const int kq  = lane & 3;           // 0..3

    // Prologue: prefetch tile0's raw f32 into stage
    int tile = blockIdx.x;
    {
        const char* src = (const char*)(x + (size_t)tile * 16384);
        #pragma unroll
        for (int j = 0; j < 8; j++) {
            int gidx = tid + j * 512;
            asm volatile("cp.async.cg.shared.global [%0], [%1], 16;"
                         :: "r"(sbase + OFF_STAGE + gidx * 16),
                            "l"(src + (size_t)gidx * 16) : "memory");
        }
    }
    CP_COMMIT();

    // Load B once (all 256 centroids), padded layout; + c_sq
    #pragma unroll
    for (int i = 0; i < 32; i++) {
        int idx = tid + i * 512;               // 0..16383
        uint32_t v = g_cent[idx];
        int row = idx >> 6, cp = idx & 63;
        ((uint32_t*)(smem + OFF_SB))[row * 68 + cp] = v;
    }
    if (tid < 256) sCsq[tid] = g_c_sq[tid];

    // ldmatrix per-lane addresses (R6-verified mapping, padded 272B stride)
    const uint32_t sA_b = sbase + OFF_SA;
    const uint32_t sB_b = sbase + OFF_SB;
    const int i8 = lane >> 3, j8 = lane & 7;
    uint32_t aAddr[2], bAddr[4];
    #pragma unroll
    for (int mt = 0; mt < 2; mt++) {
        int row = wm + mt * 16 + j8 + (i8 & 1) * 8;
        aAddr[mt] = sA_b + row * SA_STRIDE_B + (i8 >> 1) * 16;
    }
    #pragma unroll
    for (int p = 0; p < 4; p++) {
        int row = wn + p * 16 + j8 + (i8 >> 1) * 8;
        bAddr[p] = sB_b + row * SA_STRIDE_B + (i8 & 1) * 16;
    }

    for (; tile < N_TILES; tile += GRID_MAIN) {
        CP_WAIT0();
        __syncthreads();   // stage(t) + (first iter: sB/sCsq) visible

        // ---- Convert stage f32 -> sA bf16 (warp-per-row) + x_sq ----
        #pragma unroll
        for (int k = 0; k < 8; k++) {
            int row = warp + k * 16;
            float4 v = *(const float4*)(smem + OFF_STAGE + row * 512 + lane * 16);
            __nv_bfloat162 p0 = __floats2bfloat162_rn(v.x, v.y);
            __nv_bfloat162 p1 = __floats2bfloat162_rn(v.z, v.w);
            uint2 pk = make_uint2(*(uint32_t*)&p0, *(uint32_t*)&p1);
            *(uint2*)(smem + OFF_SA + row * SA_STRIDE_B + lane * 8) = pk;
            // squares from the QUANTIZED values (exact Gram identity)
            float q0 = __uint_as_float(pk.x << 16);
            float q1 = __uint_as_float(pk.x & 0xffff0000u);
            float q2 = __uint_as_float(pk.y << 16);
            float q3 = __uint_as_float(pk.y & 0xffff0000u);
            float s = fmaf(q0, q0, fmaf(q1, q1, fmaf(q2, q2, q3 * q3)));
            #pragma unroll
            for (int off = 16; off; off >>= 1) s += __shfl_xor_sync(0xffffffffu, s, off);
            if (lane == 0) sXsq[row] = s;
        }
        __syncthreads();   // sA/sXsq ready; stage reads complete

        if (tid < 128) sBat[tid] = batch[tile * 128 + tid];
        int nxt = tile + GRID_MAIN;
        if (nxt < N_TILES) {
            const char* src = (const char*)(x + (size_t)nxt * 16384);
            #pragma unroll
            for (int j = 0; j < 8; j++) {
                int gidx = tid + j * 512;
                asm volatile("cp.async.cg.shared.global [%0], [%1], 16;"
                             :: "r"(sbase + OFF_STAGE + gidx * 16),
                                "l"(src + (size_t)gidx * 16) : "memory");
            }
        }
        CP_COMMIT();
        __syncthreads();   // sBat visible

        // ---- K-loop: 8 ksteps, ldmatrix + mma (R6-verified) ----
        float acc[2][8][4];
        #pragma unroll
        for (int mt = 0; mt < 2; mt++)
            #pragma unroll
            for (int nt = 0; nt < 8; nt++)
                #pragma unroll
                for (int q = 0; q < 4; q++) acc[mt][nt][q] = 0.f;

        #pragma unroll
        for (int ks = 0; ks < 8; ks++) {
            const uint32_t koff = ks * 32;
            uint32_t afr[2][4], bfr[4][4];
            #pragma unroll
            for (int mt = 0; mt < 2; mt++) {
                asm volatile(
                    "ldmatrix.sync.aligned.m8n8.x4.shared.b16 {%0,%1,%2,%3}, [%4];\n"
                    : "=r"(afr[mt][0]), "=r"(afr[mt][1]), "=r"(afr[mt][2]), "=r"(afr[mt][3])
                    : "r"(aAddr[mt] + koff));
            }
            #pragma unroll
            for (int p = 0; p < 4; p++) {
                asm volatile(
                    "ldmatrix.sync.aligned.m8n8.x4.shared.b16 {%0,%1,%2,%3}, [%4];\n"
                    : "=r"(bfr[p][0]), "=r"(bfr[p][1]), "=r"(bfr[p][2]), "=r"(bfr[p][3])
                    : "r"(bAddr[p] + koff));
            }
            #pragma unroll
            for (int p = 0; p < 4; p++) {
                #pragma unroll
                for (int half = 0; half < 2; half++) {
                    const int nt = p * 2 + half;
                    const uint32_t b0 = bfr[p][half * 2];
                    const uint32_t b1 = bfr[p][half * 2 + 1];
                    #pragma unroll
                    for (int mt = 0; mt < 2; mt++) {
                        asm volatile(
                            "mma.sync.aligned.m16n8k16.row.col.f32.bf16.bf16.f32 "
                            "{%0,%1,%2,%3}, {%4,%5,%6,%7}, {%8,%9}, {%0,%1,%2,%3};\n"
                            : "+f"(acc[mt][nt][0]), "+f"(acc[mt][nt][1]),
                              "+f"(acc[mt][nt][2]), "+f"(acc[mt][nt][3])
                            : "r"(afr[mt][0]), "r"(afr[mt][1]), "r"(afr[mt][2]), "r"(afr[mt][3]),
                              "r"(b0), "r"(b1));
                    }
                }
            }
        }

        // ---- Epilogue: 2 chunks of 128 centroid cols ----
        #pragma unroll 1
        for (int ch = 0; ch < 2; ch++) {
            if ((wn >> 7) == ch) {
                const int cl0 = wn & 64;      // 0 or 64 within the 128-col chunk
                #pragma unroll
                for (int mt = 0; mt < 2; mt++) {
                    int r = wm + mt * 16 + gid;
                    float xs0 = sXsq[r], xs1 = sXsq[r + 8];
                    const int xr = (r & 7) << 2;   // same for r and r+8
                    #pragma unroll
                    for (int nt = 0; nt < 8; nt++) {
                        int c = cl0 + nt * 8 + kq * 2;
                        int cg = ch * 128 + c;
                        float cs0 = sCsq[cg], cs1 = sCsq[cg + 1];
                        float d00 = fsqrt_approx(fmaxf(xs0 + cs0 - 2.f * acc[mt][nt][0], 0.f));
                        float d01 = fsqrt_approx(fmaxf(xs0 + cs1 - 2.f * acc[mt][nt][1], 0.f));
                        float d10 = fsqrt_approx(fmaxf(xs1 + cs0 - 2.f * acc[mt][nt][2], 0.f));
                        float d11 = fsqrt_approx(fmaxf(xs1 + cs1 - 2.f * acc[mt][nt][3], 0.f));
                        __nv_bfloat162 h0 = __floats2bfloat162_rn(d00, d01);
                        __nv_bfloat162 h1 = __floats2bfloat162_rn(d10, d11);
                        int cp = c >> 1;
                        sDistW[r * 64 + (cp ^ xr)]       = *(uint32_t*)&h0;
                        sDistW[(r + 8) * 64 + (cp ^ xr)] = *(uint32_t*)&h1;
                    }
                }
            }
            __syncthreads();
            // segmented per-colpair reduction: 512 thr = 64 colpairs x 8 rowgroups
            {
                const int cp  = tid & 63;
                const int rb  = (tid >> 6) * 16;
                float a0 = 0.f, a1 = 0.f;
                int curg = sBat[rb];
                const int colg = ch * 128 + cp * 2;
                #pragma unroll 4
                for (int r = rb; r < rb + 16; r++) {
                    int gg = sBat[r];
                    if (gg != curg) {
                        atomicAdd(&g_sums[curg * C_NUM + colg], a0);
                        atomicAdd(&g_sums[curg * C_NUM + colg + 1], a1);
                        a0 = a1 = 0.f; curg = gg;
                    }
                    uint32_t u = sDistW[r * 64 + (cp ^ ((r & 7) << 2))];
                    __nv_bfloat162 h = *(__nv_bfloat162*)&u;
                    a0 += __bfloat162float(h.x);
                    a1 += __bfloat162float(h.y);
                }
                atomicAdd(&g_sums[curg * C_NUM + colg], a0);
                atomicAdd(&g_sums[curg * C_NUM + colg + 1], a1);
            }
            __syncthreads();
        }
    }
}

// ---------------------------------------------------------------------------
__global__ void finalize_kernel(float* __restrict__ out) {
    int g = blockIdx.x, c = threadIdx.x;
    float cnt = (float)(g_counts[g] > 1 ? g_counts[g] : 1);
    out[g * C_NUM + c] = g_sums[g * C_NUM + c] / cnt;
}

// ---------------------------------------------------------------------------
extern "C" void kernel_launch(void* const* d_in, const int* in_sizes, int n_in,
                              void* d_out, int out_size) {
    const float* x     = (const float*)d_in[0];
    const int*   batch = (const int*)d_in[1];
    const float* cent  = (const float*)d_in[2];
    float* out = (float*)d_out;

    cudaFuncSetAttribute(centroid_main_kernel,
                         cudaFuncAttributeMaxDynamicSharedMemorySize, SMEM_TOTAL);

    prep_kernel<<<256, 256>>>(cent, batch);
    centroid_main_kernel<<<GRID_MAIN, THREADS, SMEM_TOTAL>>>(x, batch);
    finalize_kernel<<<G_NUM, 256>>>(out);
}